// round 11
// baseline (speedup 1.0000x reference)
#include <cuda_runtime.h>

#define BB 512
#define TT 512
#define FF 64
#define HH 128
#define GG 512   // 4*H
#define BT (BB*TT)
#define C_OUT 10

typedef unsigned long long u64;

// ---------- packed f32x2 helpers (Blackwell FFMA2 path) ----------
__device__ __forceinline__ u64 pack2(float x, float y) {
    u64 r; asm("mov.b64 %0, {%1,%2};" : "=l"(r) : "f"(x), "f"(y)); return r;
}
__device__ __forceinline__ u64 ffma2(u64 a, u64 b, u64 c) {
    u64 d; asm("fma.rn.f32x2 %0, %1, %2, %3;" : "=l"(d) : "l"(a), "l"(b), "l"(c)); return d;
}
__device__ __forceinline__ u64 fadd2(u64 a, u64 b) {
    u64 d; asm("add.rn.f32x2 %0, %1, %2;" : "=l"(d) : "l"(a), "l"(b)); return d;
}
__device__ __forceinline__ float hadd2(u64 a) {
    float lo, hi; asm("mov.b64 {%0,%1}, %2;" : "=f"(lo), "=f"(hi) : "l"(a));
    return lo + hi;
}
__device__ __forceinline__ float lo2(u64 a) {
    float lo, hi; asm("mov.b64 {%0,%1}, %2;" : "=f"(lo), "=f"(hi) : "l"(a));
    return lo;
}
__device__ __forceinline__ float hi2(u64 a) {
    float lo, hi; asm("mov.b64 {%0,%1}, %2;" : "=f"(lo), "=f"(hi) : "l"(a));
    return hi;
}

__device__ __forceinline__ float sigm(float z) {
    return __fdividef(1.f, 1.f + __expf(-z));
}
__device__ __forceinline__ float tanh_f(float z) {
    return 1.f - __fdividef(2.f, __expf(2.f * z) + 1.f);
}

// ---------- scratch (device globals; no allocation allowed) ----------
__device__ __align__(16) float g_xp[(long)BT * GG];   // 512 MB, reused both layers
__device__ __align__(16) float g_h1[(long)BT * HH];   // 128 MB, layer-1 outputs
__device__ __align__(16) float g_last[BB * HH];
__device__ __align__(16) float g_wt4[2][64 * 256 * 4]; // packed W_hh per layer
__device__ __align__(16) float g_bias[2][GG];

// ---------- prep: pack W_hh into k-pair interleaved layout ----------
// g_wt4[L][(k2*256+t)*4 + {0,1,2,3}] = {W[2t][2k2], W[2t][2k2+1], W[2t+1][2k2], W[2t+1][2k2+1]}
__global__ void prep_kernel(const float* __restrict__ w1hh, const float* __restrict__ w2hh,
                            const float* __restrict__ b1i, const float* __restrict__ b1h,
                            const float* __restrict__ b2i, const float* __restrict__ b2h) {
    int layer = blockIdx.y;
    const float* w = layer ? w2hh : w1hh;
    int gid = blockIdx.x * blockDim.x + threadIdx.x;  // [0, 16384)
    int k2 = gid >> 8;
    int gp = gid & 255;
    int k = 2 * k2;
    float* o = &g_wt4[layer][(size_t)gid * 4];
    o[0] = w[(2 * gp) * HH + k];
    o[1] = w[(2 * gp) * HH + k + 1];
    o[2] = w[(2 * gp + 1) * HH + k];
    o[3] = w[(2 * gp + 1) * HH + k + 1];
    if (gid < GG) {
        g_bias[layer][gid] = layer ? (b2i[gid] + b2h[gid]) : (b1i[gid] + b1h[gid]);
    }
}

// ---------- x-projection GEMM (R7 version): out[BT][512] = in[BT][K] @ wih^T + bias ----------
#define GBM 128
#define GBN 128
#define GBK 32

__global__ void __launch_bounds__(256, 2) gemm_xproj2(
        const float* __restrict__ in_, const float* __restrict__ wih,
        const float* __restrict__ bias, float* __restrict__ out, int K) {
    __shared__ __align__(16) float A_s[GBK][GBM + 4];     // row stride 132 floats
    __shared__ __align__(16) u64   B_s[GBK][GBN / 2 + 2]; // (w[2n],w[2n+1]) pairs

    int tid = threadIdx.x;
    int tx = tid & 15;        // n-group
    int ty = tid >> 4;        // m-group
    long m0 = (long)blockIdx.x * GBM;
    int n0 = blockIdx.y * GBN;

    u64 acc[8][4];
#pragma unroll
    for (int i = 0; i < 8; i++)
#pragma unroll
        for (int j = 0; j < 4; j++) acc[i][j] = 0ull;

    int a_lk = (tid & 7) * 4;      // k offset for A loads (float4)
    int a_lm = tid >> 3;           // m base (0..31), +32*i
    int b_lp = tid >> 2;           // n-pair 0..63
    int b_kq = (tid & 3) * 8;      // k offset, 8 k per thread

    for (int kt = 0; kt < K; kt += GBK) {
#pragma unroll
        for (int i = 0; i < 4; i++) {
            int m = a_lm + 32 * i;
            float4 v = *(const float4*)&in_[(m0 + m) * K + kt + a_lk];
            A_s[a_lk + 0][m] = v.x;
            A_s[a_lk + 1][m] = v.y;
            A_s[a_lk + 2][m] = v.z;
            A_s[a_lk + 3][m] = v.w;
        }
        {
            int g = n0 + 2 * b_lp;
            const float* w0 = &wih[(long)g * K + kt + b_kq];
            const float* w1 = &wih[(long)(g + 1) * K + kt + b_kq];
            float4 x0 = *(const float4*)(w0);
            float4 x1 = *(const float4*)(w0 + 4);
            float4 y0 = *(const float4*)(w1);
            float4 y1 = *(const float4*)(w1 + 4);
            B_s[b_kq + 0][b_lp] = pack2(x0.x, y0.x);
            B_s[b_kq + 1][b_lp] = pack2(x0.y, y0.y);
            B_s[b_kq + 2][b_lp] = pack2(x0.z, y0.z);
            B_s[b_kq + 3][b_lp] = pack2(x0.w, y0.w);
            B_s[b_kq + 4][b_lp] = pack2(x1.x, y1.x);
            B_s[b_kq + 5][b_lp] = pack2(x1.y, y1.y);
            B_s[b_kq + 6][b_lp] = pack2(x1.z, y1.z);
            B_s[b_kq + 7][b_lp] = pack2(x1.w, y1.w);
        }
        __syncthreads();

#pragma unroll
        for (int kk = 0; kk < GBK; kk++) {
            float4 a0 = *(const float4*)&A_s[kk][ty * 4];
            float4 a1 = *(const float4*)&A_s[kk][64 + ty * 4];
            ulonglong2 bA = *(const ulonglong2*)&B_s[kk][2 * tx];
            ulonglong2 bB = *(const ulonglong2*)&B_s[kk][32 + 2 * tx];
            u64 ad;
#define GEMM_ROW(r, av) \
            ad = pack2(av, av); \
            acc[r][0] = ffma2(ad, bA.x, acc[r][0]); \
            acc[r][1] = ffma2(ad, bA.y, acc[r][1]); \
            acc[r][2] = ffma2(ad, bB.x, acc[r][2]); \
            acc[r][3] = ffma2(ad, bB.y, acc[r][3]);
            GEMM_ROW(0, a0.x)
            GEMM_ROW(1, a0.y)
            GEMM_ROW(2, a0.z)
            GEMM_ROW(3, a0.w)
            GEMM_ROW(4, a1.x)
            GEMM_ROW(5, a1.y)
            GEMM_ROW(6, a1.z)
            GEMM_ROW(7, a1.w)
#undef GEMM_ROW
        }
        __syncthreads();
    }

    const u64* bias64 = (const u64*)bias;
    u64 bv0 = bias64[n0 / 2 + 2 * tx];
    u64 bv1 = bias64[n0 / 2 + 2 * tx + 1];
    u64 bv2 = bias64[n0 / 2 + 32 + 2 * tx];
    u64 bv3 = bias64[n0 / 2 + 32 + 2 * tx + 1];
#pragma unroll
    for (int r = 0; r < 8; r++) {
        int m = (r < 4) ? (ty * 4 + r) : (64 + ty * 4 + (r - 4));
        u64* orow = (u64*)(out + (m0 + m) * GG);
        ulonglong2 s0, s1;
        s0.x = fadd2(acc[r][0], bv0); s0.y = fadd2(acc[r][1], bv1);
        s1.x = fadd2(acc[r][2], bv2); s1.y = fadd2(acc[r][3], bv3);
        *(ulonglong2*)&orow[n0 / 2 + 2 * tx] = s0;
        *(ulonglong2*)&orow[n0 / 2 + 32 + 2 * tx] = s1;
    }
}

// ---------- LSTM recurrence v5: split-k, 512 threads, 4 warps/SMSP ----------
// Thread (half, t): gate-pair t = tid&255, k-half = tid>>8 (64 k each).
// Per thread: 16 k2 of W in regs, 16 k2 in smem. Partials combined through
// the gate buffer: upper half stores partial + xp, lower half adds on top.
#define L5_SMEM_W (32 * 256 * 16)   // 131072 B: [32 k2-rows][256 pairs] ulonglong2
#define LSTM5_SMEM (L5_SMEM_W + 2048 + 8192)

__global__ void __launch_bounds__(512, 1) lstm_rec5(
        const float* __restrict__ xp, const float* __restrict__ wt4,
        float* __restrict__ out, int write_all) {
    extern __shared__ __align__(16) char smem_raw[];
    ulonglong2* wsm = (ulonglong2*)smem_raw;                           // [32][256]
    float (*hs)[HH] = (float(*)[HH])(smem_raw + L5_SMEM_W);            // [4][128]
    float (*sg)[GG] = (float(*)[GG])(smem_raw + L5_SMEM_W + 2048);     // [4][512]

    int tid = threadIdx.x;
    const int t = tid & 255;
    const int half = tid >> 8;
    int b0 = blockIdx.x * 4;

    const ulonglong2* wp = (const ulonglong2*)wt4 + t;

    // W regs: global k2 = 32*half + i, i in [0,16)
    u64 wA[16], wB[16];
#pragma unroll
    for (int i = 0; i < 16; i++) {
        ulonglong2 w = wp[(size_t)(32 * half + i) * 256];
        wA[i] = w.x;
        wB[i] = w.y;
    }
    // W smem: global k2 = 32*half + 16 + i -> row half*16 + i
    for (int i = 0; i < 16; i++) {
        wsm[(half * 16 + i) * 256 + t] = wp[(size_t)(32 * half + 16 + i) * 256];
    }

    // init h = 0 (512 threads cover [4][128] exactly)
    hs[tid >> 7][tid & 127] = 0.f;
    float c_reg = 0.f;
    __syncthreads();

    const int hb = 64 * half;   // this thread's k-range start in h

    for (int ts = 0; ts < TT; ts++) {
        // upper half owns xp (added into its partial)
        u64 xpv0 = 0, xpv1 = 0, xpv2 = 0, xpv3 = 0;
        if (half) {
            xpv0 = *(const u64*)(xp + ((long)(b0 + 0) * TT + ts) * GG + 2 * t);
            xpv1 = *(const u64*)(xp + ((long)(b0 + 1) * TT + ts) * GG + 2 * t);
            xpv2 = *(const u64*)(xp + ((long)(b0 + 2) * TT + ts) * GG + 2 * t);
            xpv3 = *(const u64*)(xp + ((long)(b0 + 3) * TT + ts) * GG + 2 * t);
        }

        u64 aA0 = 0, aA1 = 0, aA2 = 0, aA3 = 0;   // gate 2t,   batches 0..3
        u64 aB0 = 0, aB1 = 0, aB2 = 0, aB3 = 0;   // gate 2t+1, batches 0..3

        // ---- register part: k in [hb, hb+32), 8 chunks of 4 k ----
#pragma unroll
        for (int c = 0; c < 8; c++) {
            ulonglong2 h0 = *(const ulonglong2*)&hs[0][hb + 4 * c];
            ulonglong2 h1 = *(const ulonglong2*)&hs[1][hb + 4 * c];
            ulonglong2 h2 = *(const ulonglong2*)&hs[2][hb + 4 * c];
            ulonglong2 h3 = *(const ulonglong2*)&hs[3][hb + 4 * c];
            u64 wa0 = wA[2 * c], wa1 = wA[2 * c + 1];
            u64 wb0 = wB[2 * c], wb1 = wB[2 * c + 1];
            aA0 = ffma2(wa0, h0.x, aA0); aA0 = ffma2(wa1, h0.y, aA0);
            aB0 = ffma2(wb0, h0.x, aB0); aB0 = ffma2(wb1, h0.y, aB0);
            aA1 = ffma2(wa0, h1.x, aA1); aA1 = ffma2(wa1, h1.y, aA1);
            aB1 = ffma2(wb0, h1.x, aB1); aB1 = ffma2(wb1, h1.y, aB1);
            aA2 = ffma2(wa0, h2.x, aA2); aA2 = ffma2(wa1, h2.y, aA2);
            aB2 = ffma2(wb0, h2.x, aB2); aB2 = ffma2(wb1, h2.y, aB2);
            aA3 = ffma2(wa0, h3.x, aA3); aA3 = ffma2(wa1, h3.y, aA3);
            aB3 = ffma2(wb0, h3.x, aB3); aB3 = ffma2(wb1, h3.y, aB3);
        }
        // ---- smem part: k in [hb+32, hb+64), rows half*16 + {2c, 2c+1} ----
#pragma unroll
        for (int c = 0; c < 8; c++) {
            ulonglong2 w0 = wsm[(half * 16 + 2 * c) * 256 + t];
            ulonglong2 w1 = wsm[(half * 16 + 2 * c + 1) * 256 + t];
            ulonglong2 h0 = *(const ulonglong2*)&hs[0][hb + 32 + 4 * c];
            ulonglong2 h1 = *(const ulonglong2*)&hs[1][hb + 32 + 4 * c];
            ulonglong2 h2 = *(const ulonglong2*)&hs[2][hb + 32 + 4 * c];
            ulonglong2 h3 = *(const ulonglong2*)&hs[3][hb + 32 + 4 * c];
            aA0 = ffma2(w0.x, h0.x, aA0); aA0 = ffma2(w1.x, h0.y, aA0);
            aB0 = ffma2(w0.y, h0.x, aB0); aB0 = ffma2(w1.y, h0.y, aB0);
            aA1 = ffma2(w0.x, h1.x, aA1); aA1 = ffma2(w1.x, h1.y, aA1);
            aB1 = ffma2(w0.y, h1.x, aB1); aB1 = ffma2(w1.y, h1.y, aB1);
            aA2 = ffma2(w0.x, h2.x, aA2); aA2 = ffma2(w1.x, h2.y, aA2);
            aB2 = ffma2(w0.y, h2.x, aB2); aB2 = ffma2(w1.y, h2.y, aB2);
            aA3 = ffma2(w0.x, h3.x, aA3); aA3 = ffma2(w1.x, h3.y, aA3);
            aB3 = ffma2(w0.y, h3.x, aB3); aB3 = ffma2(w1.y, h3.y, aB3);
        }

        // upper half: partial + xp -> sg
        if (half) {
            ((u64*)sg[0])[t] = pack2(hadd2(aA0) + lo2(xpv0), hadd2(aB0) + hi2(xpv0));
            ((u64*)sg[1])[t] = pack2(hadd2(aA1) + lo2(xpv1), hadd2(aB1) + hi2(xpv1));
            ((u64*)sg[2])[t] = pack2(hadd2(aA2) + lo2(xpv2), hadd2(aB2) + hi2(xpv2));
            ((u64*)sg[3])[t] = pack2(hadd2(aA3) + lo2(xpv3), hadd2(aB3) + hi2(xpv3));
        }
        __syncthreads();
        // lower half: add own partial on top
        if (!half) {
            ((u64*)sg[0])[t] = fadd2(pack2(hadd2(aA0), hadd2(aB0)), ((u64*)sg[0])[t]);
            ((u64*)sg[1])[t] = fadd2(pack2(hadd2(aA1), hadd2(aB1)), ((u64*)sg[1])[t]);
            ((u64*)sg[2])[t] = fadd2(pack2(hadd2(aA2), hadd2(aB2)), ((u64*)sg[2])[t]);
            ((u64*)sg[3])[t] = fadd2(pack2(hadd2(aA3), hadd2(aB3)), ((u64*)sg[3])[t]);
        }
        __syncthreads();

        // state update: 512 hidden units / 512 threads = 1 each
        {
            int b = tid >> 7;
            int j = tid & 127;
            float zi = sg[b][j];
            float zf = sg[b][HH + j];
            float zg = sg[b][2 * HH + j];
            float zo = sg[b][3 * HH + j];
            float iv = sigm(zi);
            float fv = sigm(zf);
            float gv = tanh_f(zg);
            float ov = sigm(zo);
            float c = fv * c_reg + iv * gv;
            c_reg = c;
            float h = ov * tanh_f(c);
            hs[b][j] = h;
            if (write_all) {
                out[((long)(b0 + b) * TT + ts) * HH + j] = h;
            } else if (ts == TT - 1) {
                out[(b0 + b) * HH + j] = h;
            }
        }
        __syncthreads();
    }
}

// ---------- final FC + sigmoid: out[512][10] ----------
__global__ void fc_kernel(const float* __restrict__ last, const float* __restrict__ wfc,
                          const float* __restrict__ bfc, float* __restrict__ out) {
    int b = blockIdx.x;
    int lane = threadIdx.x;  // 32 threads
    float4 v = ((const float4*)(last + b * HH))[lane];
    for (int c = 0; c < C_OUT; c++) {
        float4 w = ((const float4*)(wfc + c * HH))[lane];
        float s = v.x * w.x + v.y * w.y + v.z * w.z + v.w * w.w;
#pragma unroll
        for (int off = 16; off; off >>= 1) s += __shfl_xor_sync(0xffffffffu, s, off);
        if (lane == 0) out[b * C_OUT + c] = sigm(s + bfc[c]);
    }
}

extern "C" void kernel_launch(void* const* d_in, const int* in_sizes, int n_in,
                              void* d_out, int out_size) {
    const float* x     = (const float*)d_in[0];
    const float* w1_ih = (const float*)d_in[1];
    const float* w1_hh = (const float*)d_in[2];
    const float* b1_ih = (const float*)d_in[3];
    const float* b1_hh = (const float*)d_in[4];
    const float* w2_ih = (const float*)d_in[5];
    const float* w2_hh = (const float*)d_in[6];
    const float* b2_ih = (const float*)d_in[7];
    const float* b2_hh = (const float*)d_in[8];
    const float* w_fc  = (const float*)d_in[9];
    const float* b_fc  = (const float*)d_in[10];
    float* out = (float*)d_out;

    float *xp, *h1, *last, *wt4, *bias;
    cudaGetSymbolAddress((void**)&xp,   g_xp);
    cudaGetSymbolAddress((void**)&h1,   g_h1);
    cudaGetSymbolAddress((void**)&last, g_last);
    cudaGetSymbolAddress((void**)&wt4,  g_wt4);
    cudaGetSymbolAddress((void**)&bias, g_bias);

    const float* wt4_1  = wt4;
    const float* wt4_2  = wt4 + 64 * 256 * 4;
    const float* bias_1 = bias;
    const float* bias_2 = bias + GG;

    cudaFuncSetAttribute(lstm_rec5, cudaFuncAttributeMaxDynamicSharedMemorySize,
                         LSTM5_SMEM);

    prep_kernel<<<dim3(64, 2), 256>>>(w1_hh, w2_hh, b1_ih, b1_hh, b2_ih, b2_hh);

    // Layer 1
    gemm_xproj2<<<dim3(BT / GBM, GG / GBN), 256>>>(x, w1_ih, bias_1, xp, FF);
    lstm_rec5<<<BB / 4, 512, LSTM5_SMEM>>>(xp, wt4_1, h1, 1);

    // Layer 2
    gemm_xproj2<<<dim3(BT / GBM, GG / GBN), 256>>>(h1, w2_ih, bias_2, xp, HH);
    lstm_rec5<<<BB / 4, 512, LSTM5_SMEM>>>(xp, wt4_2, last, 0);

    // FC head
    fc_kernel<<<BB, 32>>>(last, w_fc, b_fc, out);
}

// round 13
// speedup vs baseline: 1.1777x; 1.1777x over previous
#include <cuda_runtime.h>

#define BB 512
#define TT 512
#define FF 64
#define HH 128
#define GG 512   // 4*H
#define BT (BB*TT)
#define C_OUT 10

typedef unsigned long long u64;

// ---------- packed f32x2 helpers (Blackwell FFMA2 path) ----------
__device__ __forceinline__ u64 pack2(float x, float y) {
    u64 r; asm("mov.b64 %0, {%1,%2};" : "=l"(r) : "f"(x), "f"(y)); return r;
}
__device__ __forceinline__ u64 ffma2(u64 a, u64 b, u64 c) {
    u64 d; asm("fma.rn.f32x2 %0, %1, %2, %3;" : "=l"(d) : "l"(a), "l"(b), "l"(c)); return d;
}
__device__ __forceinline__ u64 fadd2(u64 a, u64 b) {
    u64 d; asm("add.rn.f32x2 %0, %1, %2;" : "=l"(d) : "l"(a), "l"(b)); return d;
}
__device__ __forceinline__ float hadd2(u64 a) {
    float lo, hi; asm("mov.b64 {%0,%1}, %2;" : "=f"(lo), "=f"(hi) : "l"(a));
    return lo + hi;
}
__device__ __forceinline__ float lo2(u64 a) {
    float lo, hi; asm("mov.b64 {%0,%1}, %2;" : "=f"(lo), "=f"(hi) : "l"(a));
    return lo;
}
__device__ __forceinline__ float hi2(u64 a) {
    float lo, hi; asm("mov.b64 {%0,%1}, %2;" : "=f"(lo), "=f"(hi) : "l"(a));
    return hi;
}

__device__ __forceinline__ float sigm(float z) {
    return __fdividef(1.f, 1.f + __expf(-z));
}
__device__ __forceinline__ float tanh_f(float z) {
    return 1.f - __fdividef(2.f, __expf(2.f * z) + 1.f);
}

// ---------- scratch (device globals; no allocation allowed) ----------
__device__ __align__(16) float g_xp[(long)BT * GG];   // 512 MB, reused both layers
__device__ __align__(16) float g_h1[(long)BT * HH];   // 128 MB, layer-1 outputs
__device__ __align__(16) float g_last[BB * HH];
__device__ __align__(16) float g_wt4[2][64 * 256 * 4]; // packed W_hh per layer
__device__ __align__(16) float g_bias[2][GG];

// ---------- prep: pack W_hh into k-pair interleaved layout ----------
// g_wt4[L][(k2*256+t)*4 + {0,1,2,3}] = {W[2t][2k2], W[2t][2k2+1], W[2t+1][2k2], W[2t+1][2k2+1]}
__global__ void prep_kernel(const float* __restrict__ w1hh, const float* __restrict__ w2hh,
                            const float* __restrict__ b1i, const float* __restrict__ b1h,
                            const float* __restrict__ b2i, const float* __restrict__ b2h) {
    int layer = blockIdx.y;
    const float* w = layer ? w2hh : w1hh;
    int gid = blockIdx.x * blockDim.x + threadIdx.x;  // [0, 16384)
    int k2 = gid >> 8;
    int gp = gid & 255;
    int k = 2 * k2;
    float* o = &g_wt4[layer][(size_t)gid * 4];
    o[0] = w[(2 * gp) * HH + k];
    o[1] = w[(2 * gp) * HH + k + 1];
    o[2] = w[(2 * gp + 1) * HH + k];
    o[3] = w[(2 * gp + 1) * HH + k + 1];
    if (gid < GG) {
        g_bias[layer][gid] = layer ? (b2i[gid] + b2h[gid]) : (b1i[gid] + b1h[gid]);
    }
}

// ---------- x-projection GEMM v4: double-buffered, BK=16, one barrier/tile ----------
#define GBM 128
#define GBN 128
#define DBK 16

__global__ void __launch_bounds__(256, 2) gemm_db(
        const float* __restrict__ in_, const float* __restrict__ wih,
        const float* __restrict__ bias, float* __restrict__ out, int K) {
    __shared__ __align__(16) float A_s[2][DBK][GBM + 4];     // 2 x 16 x 132 floats
    __shared__ __align__(16) u64   B_s[2][DBK][GBN / 2 + 2]; // 2 x 16 x 66 pairs

    int tid = threadIdx.x;
    int tx = tid & 15;        // n-group
    int ty = tid >> 4;        // m-group
    long m0 = (long)blockIdx.x * GBM;
    int n0 = blockIdx.y * GBN;

    u64 acc[8][4];
#pragma unroll
    for (int i = 0; i < 8; i++)
#pragma unroll
        for (int j = 0; j < 4; j++) acc[i][j] = 0ull;

    // loader indices
    int a_lk = (tid & 3) * 4;      // k offset (float4)
    int a_lm = tid >> 2;           // m 0..63 (+64 for second row)
    int b_p  = tid >> 2;           // n-pair 0..63
    int b_q  = (tid & 3) * 4;      // k offset: 4 k per thread

    const int nt = K / DBK;

    // prologue: load tile 0 into buffer 0
    {
        float4 v0 = *(const float4*)&in_[(m0 + a_lm) * K + a_lk];
        float4 v1 = *(const float4*)&in_[(m0 + a_lm + 64) * K + a_lk];
        int g = n0 + 2 * b_p;
        float4 x = *(const float4*)&wih[(long)g * K + b_q];
        float4 y = *(const float4*)&wih[(long)(g + 1) * K + b_q];
        A_s[0][a_lk + 0][a_lm] = v0.x;
        A_s[0][a_lk + 1][a_lm] = v0.y;
        A_s[0][a_lk + 2][a_lm] = v0.z;
        A_s[0][a_lk + 3][a_lm] = v0.w;
        A_s[0][a_lk + 0][a_lm + 64] = v1.x;
        A_s[0][a_lk + 1][a_lm + 64] = v1.y;
        A_s[0][a_lk + 2][a_lm + 64] = v1.z;
        A_s[0][a_lk + 3][a_lm + 64] = v1.w;
        B_s[0][b_q + 0][b_p] = pack2(x.x, y.x);
        B_s[0][b_q + 1][b_p] = pack2(x.y, y.y);
        B_s[0][b_q + 2][b_p] = pack2(x.z, y.z);
        B_s[0][b_q + 3][b_p] = pack2(x.w, y.w);
    }
    __syncthreads();

    for (int it = 0; it < nt; it++) {
        int buf = it & 1;
        // issue next-tile loads first (latency overlapped with FFMA block)
        float4 v0, v1, x, y;
        bool have_next = (it + 1 < nt);
        if (have_next) {
            int kt = (it + 1) * DBK;
            v0 = *(const float4*)&in_[(m0 + a_lm) * K + kt + a_lk];
            v1 = *(const float4*)&in_[(m0 + a_lm + 64) * K + kt + a_lk];
            int g = n0 + 2 * b_p;
            x = *(const float4*)&wih[(long)g * K + kt + b_q];
            y = *(const float4*)&wih[(long)(g + 1) * K + kt + b_q];
        }

#pragma unroll
        for (int kk = 0; kk < DBK; kk++) {
            float4 a0 = *(const float4*)&A_s[buf][kk][ty * 4];
            float4 a1 = *(const float4*)&A_s[buf][kk][64 + ty * 4];
            ulonglong2 bA = *(const ulonglong2*)&B_s[buf][kk][2 * tx];
            ulonglong2 bB = *(const ulonglong2*)&B_s[buf][kk][32 + 2 * tx];
            u64 ad;
#define GEMM_ROW(r, av) \
            ad = pack2(av, av); \
            acc[r][0] = ffma2(ad, bA.x, acc[r][0]); \
            acc[r][1] = ffma2(ad, bA.y, acc[r][1]); \
            acc[r][2] = ffma2(ad, bB.x, acc[r][2]); \
            acc[r][3] = ffma2(ad, bB.y, acc[r][3]);
            GEMM_ROW(0, a0.x)
            GEMM_ROW(1, a0.y)
            GEMM_ROW(2, a0.z)
            GEMM_ROW(3, a0.w)
            GEMM_ROW(4, a1.x)
            GEMM_ROW(5, a1.y)
            GEMM_ROW(6, a1.z)
            GEMM_ROW(7, a1.w)
#undef GEMM_ROW
        }

        if (have_next) {
            int nb = buf ^ 1;
            A_s[nb][a_lk + 0][a_lm] = v0.x;
            A_s[nb][a_lk + 1][a_lm] = v0.y;
            A_s[nb][a_lk + 2][a_lm] = v0.z;
            A_s[nb][a_lk + 3][a_lm] = v0.w;
            A_s[nb][a_lk + 0][a_lm + 64] = v1.x;
            A_s[nb][a_lk + 1][a_lm + 64] = v1.y;
            A_s[nb][a_lk + 2][a_lm + 64] = v1.z;
            A_s[nb][a_lk + 3][a_lm + 64] = v1.w;
            B_s[nb][b_q + 0][b_p] = pack2(x.x, y.x);
            B_s[nb][b_q + 1][b_p] = pack2(x.y, y.y);
            B_s[nb][b_q + 2][b_p] = pack2(x.z, y.z);
            B_s[nb][b_q + 3][b_p] = pack2(x.w, y.w);
        }
        __syncthreads();
    }

    // ---- epilogue: + bias, packed 16B stores ----
    const u64* bias64 = (const u64*)bias;
    u64 bv0 = bias64[n0 / 2 + 2 * tx];
    u64 bv1 = bias64[n0 / 2 + 2 * tx + 1];
    u64 bv2 = bias64[n0 / 2 + 32 + 2 * tx];
    u64 bv3 = bias64[n0 / 2 + 32 + 2 * tx + 1];
#pragma unroll
    for (int r = 0; r < 8; r++) {
        int m = (r < 4) ? (ty * 4 + r) : (64 + ty * 4 + (r - 4));
        u64* orow = (u64*)(out + (m0 + m) * GG);
        ulonglong2 s0, s1;
        s0.x = fadd2(acc[r][0], bv0); s0.y = fadd2(acc[r][1], bv1);
        s1.x = fadd2(acc[r][2], bv2); s1.y = fadd2(acc[r][3], bv3);
        *(ulonglong2*)&orow[n0 / 2 + 2 * tx] = s0;
        *(ulonglong2*)&orow[n0 / 2 + 32 + 2 * tx] = s1;
    }
}

// ---------- LSTM recurrence v6: R7 structure, W split 88 k regs / 40 k smem ----------
// 1 CTA = 4 batch rows, 256 threads, thread t owns gates (2t, 2t+1).
// Accumulators are f32x2 over (k, k+1). h stored as plain floats; one 16B
// broadcast LDS yields 4 k = two ready f32x2 operands.
#define WREG_K2 44                      // k2 in [0,44) -> k in [0,88) in registers
#define WSM_K2  (64 - WREG_K2)          // 20 k2-rows in smem
#define LSTM_SMEM_BYTES (WSM_K2 * 256 * 16 + 2048 + 8192)

__global__ void __launch_bounds__(256, 1) lstm_rec6(
        const float* __restrict__ xp, const float* __restrict__ wt4,
        float* __restrict__ out, int write_all) {
    extern __shared__ __align__(16) char smem_raw[];
    ulonglong2* wsm = (ulonglong2*)smem_raw;                             // [20][256]
    float (*hs)[HH] = (float(*)[HH])(smem_raw + WSM_K2 * 256 * 16);      // [4][128]
    float (*sg)[GG] = (float(*)[GG])(smem_raw + WSM_K2 * 256 * 16 + 2048);

    int tid = threadIdx.x;
    int b0 = blockIdx.x * 4;
    const int t = tid;

    const ulonglong2* wp = (const ulonglong2*)wt4 + t;

    // W register portion: k2 in [0,44)
    u64 wA[WREG_K2], wB[WREG_K2];
#pragma unroll
    for (int k2 = 0; k2 < WREG_K2; k2++) {
        ulonglong2 w = wp[(size_t)k2 * 256];
        wA[k2] = w.x;
        wB[k2] = w.y;
    }
    // W smem portion: k2 in [44,64)
    for (int k2 = 0; k2 < WSM_K2; k2++) {
        wsm[k2 * 256 + t] = wp[(size_t)(WREG_K2 + k2) * 256];
    }

    // init h = 0
    hs[0][tid & 127] = 0.f; hs[1][tid & 127] = 0.f;
    hs[2][tid & 127] = 0.f; hs[3][tid & 127] = 0.f;
    float c_reg[2] = {0.f, 0.f};
    __syncthreads();

    for (int tstep = 0; tstep < TT; tstep++) {
        // xp loads first (independent of h -> hidden behind dot loop)
        u64 xpv0 = *(const u64*)(xp + ((long)(b0 + 0) * TT + tstep) * GG + 2 * t);
        u64 xpv1 = *(const u64*)(xp + ((long)(b0 + 1) * TT + tstep) * GG + 2 * t);
        u64 xpv2 = *(const u64*)(xp + ((long)(b0 + 2) * TT + tstep) * GG + 2 * t);
        u64 xpv3 = *(const u64*)(xp + ((long)(b0 + 3) * TT + tstep) * GG + 2 * t);

        u64 aA0 = 0, aA1 = 0, aA2 = 0, aA3 = 0;   // gate 2t,   batches 0..3
        u64 aB0 = 0, aB1 = 0, aB2 = 0, aB3 = 0;   // gate 2t+1, batches 0..3

        // ---- register part: k in [0,88), 22 chunks of 4 k ----
#pragma unroll
        for (int c = 0; c < WREG_K2 / 2; c++) {
            ulonglong2 h0 = *(const ulonglong2*)&hs[0][4 * c];
            ulonglong2 h1 = *(const ulonglong2*)&hs[1][4 * c];
            ulonglong2 h2 = *(const ulonglong2*)&hs[2][4 * c];
            ulonglong2 h3 = *(const ulonglong2*)&hs[3][4 * c];
            u64 wa0 = wA[2 * c], wa1 = wA[2 * c + 1];
            u64 wb0 = wB[2 * c], wb1 = wB[2 * c + 1];
            aA0 = ffma2(wa0, h0.x, aA0); aA0 = ffma2(wa1, h0.y, aA0);
            aB0 = ffma2(wb0, h0.x, aB0); aB0 = ffma2(wb1, h0.y, aB0);
            aA1 = ffma2(wa0, h1.x, aA1); aA1 = ffma2(wa1, h1.y, aA1);
            aB1 = ffma2(wb0, h1.x, aB1); aB1 = ffma2(wb1, h1.y, aB1);
            aA2 = ffma2(wa0, h2.x, aA2); aA2 = ffma2(wa1, h2.y, aA2);
            aB2 = ffma2(wb0, h2.x, aB2); aB2 = ffma2(wb1, h2.y, aB2);
            aA3 = ffma2(wa0, h3.x, aA3); aA3 = ffma2(wa1, h3.y, aA3);
            aB3 = ffma2(wb0, h3.x, aB3); aB3 = ffma2(wb1, h3.y, aB3);
        }
        // ---- smem part: k in [88,128), 10 chunks of 4 k ----
#pragma unroll
        for (int c = 0; c < WSM_K2 / 2; c++) {
            ulonglong2 w0 = wsm[(2 * c) * 256 + t];
            ulonglong2 w1 = wsm[(2 * c + 1) * 256 + t];
            ulonglong2 h0 = *(const ulonglong2*)&hs[0][2 * WREG_K2 + 4 * c];
            ulonglong2 h1 = *(const ulonglong2*)&hs[1][2 * WREG_K2 + 4 * c];
            ulonglong2 h2 = *(const ulonglong2*)&hs[2][2 * WREG_K2 + 4 * c];
            ulonglong2 h3 = *(const ulonglong2*)&hs[3][2 * WREG_K2 + 4 * c];
            aA0 = ffma2(w0.x, h0.x, aA0); aA0 = ffma2(w1.x, h0.y, aA0);
            aB0 = ffma2(w0.y, h0.x, aB0); aB0 = ffma2(w1.y, h0.y, aB0);
            aA1 = ffma2(w0.x, h1.x, aA1); aA1 = ffma2(w1.x, h1.y, aA1);
            aB1 = ffma2(w0.y, h1.x, aB1); aB1 = ffma2(w1.y, h1.y, aB1);
            aA2 = ffma2(w0.x, h2.x, aA2); aA2 = ffma2(w1.x, h2.y, aA2);
            aB2 = ffma2(w0.y, h2.x, aB2); aB2 = ffma2(w1.y, h2.y, aB2);
            aA3 = ffma2(w0.x, h3.x, aA3); aA3 = ffma2(w1.x, h3.y, aA3);
            aB3 = ffma2(w0.y, h3.x, aB3); aB3 = ffma2(w1.y, h3.y, aB3);
        }

        // horizontal add + xp, store gate pair as u64
        ((u64*)sg[0])[t] = pack2(hadd2(aA0) + lo2(xpv0), hadd2(aB0) + hi2(xpv0));
        ((u64*)sg[1])[t] = pack2(hadd2(aA1) + lo2(xpv1), hadd2(aB1) + hi2(xpv1));
        ((u64*)sg[2])[t] = pack2(hadd2(aA2) + lo2(xpv2), hadd2(aB2) + hi2(xpv2));
        ((u64*)sg[3])[t] = pack2(hadd2(aA3) + lo2(xpv3), hadd2(aB3) + hi2(xpv3));
        __syncthreads();

        // state update: 512 hidden units / 256 threads = 2 each (c in regs)
#pragma unroll
        for (int u = 0; u < 2; u++) {
            int idx = tid + u * 256;
            int b = idx >> 7;
            int j = idx & 127;
            float zi = sg[b][j];
            float zf = sg[b][HH + j];
            float zg = sg[b][2 * HH + j];
            float zo = sg[b][3 * HH + j];
            float iv = sigm(zi);
            float fv = sigm(zf);
            float gv = tanh_f(zg);
            float ov = sigm(zo);
            float c = fv * c_reg[u] + iv * gv;
            c_reg[u] = c;
            float h = ov * tanh_f(c);
            hs[b][j] = h;
            if (write_all) {
                out[((long)(b0 + b) * TT + tstep) * HH + j] = h;
            } else if (tstep == TT - 1) {
                out[(b0 + b) * HH + j] = h;
            }
        }
        __syncthreads();
    }
}

// ---------- final FC + sigmoid: out[512][10] ----------
__global__ void fc_kernel(const float* __restrict__ last, const float* __restrict__ wfc,
                          const float* __restrict__ bfc, float* __restrict__ out) {
    int b = blockIdx.x;
    int lane = threadIdx.x;  // 32 threads
    float4 v = ((const float4*)(last + b * HH))[lane];
    for (int c = 0; c < C_OUT; c++) {
        float4 w = ((const float4*)(wfc + c * HH))[lane];
        float s = v.x * w.x + v.y * w.y + v.z * w.z + v.w * w.w;
#pragma unroll
        for (int off = 16; off; off >>= 1) s += __shfl_xor_sync(0xffffffffu, s, off);
        if (lane == 0) out[b * C_OUT + c] = sigm(s + bfc[c]);
    }
}

extern "C" void kernel_launch(void* const* d_in, const int* in_sizes, int n_in,
                              void* d_out, int out_size) {
    const float* x     = (const float*)d_in[0];
    const float* w1_ih = (const float*)d_in[1];
    const float* w1_hh = (const float*)d_in[2];
    const float* b1_ih = (const float*)d_in[3];
    const float* b1_hh = (const float*)d_in[4];
    const float* w2_ih = (const float*)d_in[5];
    const float* w2_hh = (const float*)d_in[6];
    const float* b2_ih = (const float*)d_in[7];
    const float* b2_hh = (const float*)d_in[8];
    const float* w_fc  = (const float*)d_in[9];
    const float* b_fc  = (const float*)d_in[10];
    float* out = (float*)d_out;

    float *xp, *h1, *last, *wt4, *bias;
    cudaGetSymbolAddress((void**)&xp,   g_xp);
    cudaGetSymbolAddress((void**)&h1,   g_h1);
    cudaGetSymbolAddress((void**)&last, g_last);
    cudaGetSymbolAddress((void**)&wt4,  g_wt4);
    cudaGetSymbolAddress((void**)&bias, g_bias);

    const float* wt4_1  = wt4;
    const float* wt4_2  = wt4 + 64 * 256 * 4;
    const float* bias_1 = bias;
    const float* bias_2 = bias + GG;

    cudaFuncSetAttribute(lstm_rec6, cudaFuncAttributeMaxDynamicSharedMemorySize,
                         LSTM_SMEM_BYTES);

    prep_kernel<<<dim3(64, 2), 256>>>(w1_hh, w2_hh, b1_ih, b1_hh, b2_ih, b2_hh);

    // Layer 1
    gemm_db<<<dim3(BT / GBM, GG / GBN), 256>>>(x, w1_ih, bias_1, xp, FF);
    lstm_rec6<<<BB / 4, 256, LSTM_SMEM_BYTES>>>(xp, wt4_1, h1, 1);

    // Layer 2
    gemm_db<<<dim3(BT / GBM, GG / GBN), 256>>>(h1, w2_ih, bias_2, xp, HH);
    lstm_rec6<<<BB / 4, 256, LSTM_SMEM_BYTES>>>(xp, wt4_2, last, 0);

    // FC head
    fc_kernel<<<BB, 32>>>(last, w_fc, b_fc, out);
}